// round 15
// baseline (speedup 1.0000x reference)
#include <cuda_runtime.h>
#include <cuda_bf16.h>

// STN_fixTheta: fused 8x nearest-upsample + dual bilinear grid_sample.
// gt: [8,1,128,256] f32, theta: [8,6] f32.
// out: box [8,1,1024,2048] f32 followed by boxy [8,1,1024,2048] f32.
//
// Fast path: a thread's 8 pixels span <=3x3 gt texels; load once, per-pixel
// saturate-weighted separable blend (exact at fp32). Box loads issued FIRST,
// boxy computed+stored while they are in flight (pipelined chains).

namespace {
constexpr int NB  = 8;
constexpr int HIN = 128;
constexpr int WIN = 256;
constexpr int HO  = 1024;
constexpr int WO  = 2048;

// floor via 2^23 bias
__device__ __forceinline__ void ffloor(float x, float& f, int& i) {
    const float MAGIC = 12582912.0f;            // 1.5 * 2^23
    float tt = x + MAGIC;
    float r  = tt - MAGIC;
    int   ri = __float_as_int(tt) - 0x4B400000;
    if (r > x) { r -= 1.0f; ri -= 1; }
    f = r; i = ri;
}

__global__ __launch_bounds__(256, 8) void stn_kernel(
    const float* __restrict__ gt,
    const float* __restrict__ theta,
    float* __restrict__ out)
{
    const int tid  = threadIdx.x;
    const int w    = tid >> 5;
    const int lane = tid & 31;
    const int lx   = lane & 7;           // 8 lanes in x
    const int ly   = lane >> 3;          // 4 rows in y
    const int wx   = w & 1;
    const int wy   = w >> 1;

    const int xo0 = blockIdx.x * 128 + wx * 64 + lx * 8;
    const int yo  = blockIdx.y * 16  + wy * 4  + ly;
    const int b   = blockIdx.z;

    const float2 th01 = __ldg(reinterpret_cast<const float2*>(theta + b * 6 + 0));
    const float2 th23 = __ldg(reinterpret_cast<const float2*>(theta + b * 6 + 2));
    const float2 th45 = __ldg(reinterpret_cast<const float2*>(theta + b * 6 + 4));
    const float t0 = th01.x, t1 = th01.y, t2 = th23.x, t3 = th23.y;
    const float t4 = th45.x, t5 = th45.y;

    const float ys = (yo + 0.5f) * (2.0f / HO) - 1.0f;
    const float* __restrict__ g = gt + b * (HIN * WIN);
    const long long pix = ((long long)b * HO + yo) * WO + xo0;
    float4* ob = reinterpret_cast<float4*>(out + pix);
    float4* oy = reinterpret_cast<float4*>(out + (long long)NB * HO * WO + pix);

    // ---------------- boxy: precompute coordinates (no loads yet) ----------
    float bwA = 0.0f, bwB = 0.0f;
    int   bo0 = 0,    bo1 = 0;
    {
        const float gyy  = fmaf(t4, ys, t5);
        const float iyy  = (fmaf(gyy, (float)HO, (float)HO) - 1.0f) * 0.5f;
        float iy0f; int iy0y;
        ffloor(iyy, iy0f, iy0y);
        const float wyy = iyy - iy0f;
        const bool ok0  = (unsigned)iy0y < (unsigned)HO;
        const bool ok1  = (unsigned)(iy0y + 1) < (unsigned)HO;
        const int  xc   = xo0 >> 3;
        bo0 = ((min(max(iy0y, 0), HO - 1)) >> 3) * WIN + xc;
        bo1 = ((min(max(iy0y + 1, 0), HO - 1)) >> 3) * WIN + xc;
        bwA = ok0 ? (1.0f - wyy) : 0.0f;
        bwB = ok1 ? wyy : 0.0f;
    }
    // boxy loads + compute + store (call site placed to overlap box loads)
    auto do_boxy = [&]() {
        const float vy = bwA * g[bo0] + bwB * g[bo1];
        const float4 vy4 = make_float4(vy, vy, vy, vy);
        oy[0] = vy4;
        oy[1] = vy4;
    };

    // ---------------- box coordinate base + classification -----------------
    const float xs0 = (xo0 + 0.5f) * (2.0f / WO) - 1.0f;
    const float gx0 = fmaf(t0, xs0, fmaf(t1, ys, t2));
    const float gy0 = fmaf(t3, xs0, fmaf(t4, ys, t5));
    const float ixb = (fmaf(gx0, (float)WO, (float)WO) - 1.0f) * 0.5f;
    const float iyb = (fmaf(gy0, (float)HO, (float)HO) - 1.0f) * 0.5f;
    const float sx  = t0;           // d ix / d xo
    const float sy  = t3 * 0.5f;    // d iy / d xo

    const float ix7 = fmaf(7.0f, sx, ixb);
    const float iy7 = fmaf(7.0f, sy, iyb);
    const float ixmin = fminf(ixb, ix7), ixmax = fmaxf(ixb, ix7);
    const float iymin = fminf(iyb, iy7), iymax = fmaxf(iyb, iy7);

    const bool interior = (ixmin >= 0.0f) && (ixmax < (float)(WO - 1)) &&
                          (iymin >= 0.0f) && (iymax < (float)(HO - 1));

    if (ixmax < -1.0f || ixmin >= (float)WO || iymax < -1.0f || iymin >= (float)HO) {
        do_boxy();
        const float4 z = make_float4(0.0f, 0.0f, 0.0f, 0.0f);
        ob[0] = z;
        ob[1] = z;
        return;
    }

    if (interior) {
        const int xlo = ((int)ixmin) >> 3;
        const int xhi = (((int)ixmax) + 1) >> 3;
        const int ylo = ((int)iymin) >> 3;
        const int yhi = (((int)iymax) + 1) >> 3;

        if ((xhi - xlo) <= 2 && (yhi - ylo) <= 2) {
            // -------- register 3x3 fast path: issue 9 loads FIRST --------
            const int x1i = min(xlo + 1, WIN - 1);
            const int x2i = min(xlo + 2, WIN - 1);
            const int y1i = min(ylo + 1, HIN - 1);
            const int y2i = min(ylo + 2, HIN - 1);
            const float* r0 = g + ylo * WIN;
            const float* r1 = g + y1i * WIN;
            const float* r2 = g + y2i * WIN;
            const float a00 = r0[xlo], a01 = r0[x1i], a02 = r0[x2i];
            const float a10 = r1[xlo], a11 = r1[x1i], a12 = r1[x2i];
            const float a20 = r2[xlo], a21 = r2[x1i], a22 = r2[x2i];

            // overlap: boxy loads/compute/store while 3x3 lands
            do_boxy();

            const float d00 = a01 - a00, d01 = a02 - a01;
            const float d10 = a11 - a10, d11 = a12 - a11;
            const float d20 = a21 - a20, d21 = a22 - a21;
            const float cx1 = (float)(8 * xlo + 7), cx2 = cx1 + 8.0f;
            const float cy1 = (float)(8 * ylo + 7), cy2 = cy1 + 8.0f;
            #pragma unroll
            for (int h = 0; h < 2; ++h) {
                float v[4];
                #pragma unroll
                for (int k = 0; k < 4; ++k) {
                    const int   j   = h * 4 + k;
                    const float ix  = fmaf((float)j, sx, ixb);
                    const float iy  = fmaf((float)j, sy, iyb);
                    const float Wx1 = __saturatef(ix - cx1);
                    const float Wx2 = __saturatef(ix - cx2);
                    const float Wy1 = __saturatef(iy - cy1);
                    const float Wy2 = __saturatef(iy - cy2);
                    const float u0 = fmaf(Wx2, d01, fmaf(Wx1, d00, a00));
                    const float u1 = fmaf(Wx2, d11, fmaf(Wx1, d10, a10));
                    const float u2 = fmaf(Wx2, d21, fmaf(Wx1, d20, a20));
                    const float vv = fmaf(Wy1, u1 - u0, u0);
                    v[k] = fmaf(Wy2, u2 - u1, vv);
                }
                ob[h] = make_float4(v[0], v[1], v[2], v[3]);
            }
        } else {
            // -------- generic interior (batched global loads) --------
            do_boxy();
            #pragma unroll
            for (int h = 0; h < 2; ++h) {
                int   o00[4], o10[4], o01[4], o11[4];
                float fwx[4], fwy[4];
                #pragma unroll
                for (int k = 0; k < 4; ++k) {
                    const int   j  = h * 4 + k;
                    const float ix = fmaf((float)j, sx, ixb);
                    const float iy = fmaf((float)j, sy, iyb);
                    float fx, fy; int ix0, iy0;
                    ffloor(ix, fx, ix0);
                    ffloor(iy, fy, iy0);
                    fwx[k] = ix - fx;
                    fwy[k] = iy - fy;
                    const int x0 = ix0 >> 3;
                    const int x1 = (ix0 + 1) >> 3;
                    const int y0 = iy0 >> 3;
                    const int y1 = (iy0 + 1) >> 3;
                    o00[k] = (y0 << 8) + x0;
                    o10[k] = (y0 << 8) + x1;
                    o01[k] = (y1 << 8) + x0;
                    o11[k] = (y1 << 8) + x1;
                }
                float l00[4], l10[4], l01[4], l11[4];
                #pragma unroll
                for (int k = 0; k < 4; ++k) {
                    l00[k] = g[o00[k]];
                    l10[k] = g[o10[k]];
                    l01[k] = g[o01[k]];
                    l11[k] = g[o11[k]];
                }
                float v[4];
                #pragma unroll
                for (int k = 0; k < 4; ++k) {
                    const float a  = fmaf(fwx[k], l10[k] - l00[k], l00[k]);
                    const float cc = fmaf(fwx[k], l11[k] - l01[k], l01[k]);
                    v[k] = fmaf(fwy[k], cc - a, a);
                }
                ob[h] = make_float4(v[0], v[1], v[2], v[3]);
            }
        }
    } else {
        // -------- edge/mixed: general predicated path (rare) --------
        do_boxy();
        #pragma unroll
        for (int h = 0; h < 2; ++h) {
            float v[4];
            #pragma unroll
            for (int k = 0; k < 4; ++k) {
                const int   j  = h * 4 + k;
                const float ix = fmaf((float)j, sx, ixb);
                const float iy = fmaf((float)j, sy, iyb);
                float fx, fy; int ix0, iy0;
                ffloor(ix, fx, ix0);
                ffloor(iy, fy, iy0);
                const float wx_ = ix - fx;
                const float wy_ = iy - fy;
                const bool xv0 = (unsigned)ix0       < (unsigned)WO;
                const bool xv1 = (unsigned)(ix0 + 1) < (unsigned)WO;
                const bool yv0 = (unsigned)iy0       < (unsigned)HO;
                const bool yv1 = (unsigned)(iy0 + 1) < (unsigned)HO;
                const int x0 = (min(max(ix0, 0), WO - 1)) >> 3;
                const int x1 = (min(max(ix0 + 1, 0), WO - 1)) >> 3;
                const int y0 = (min(max(iy0, 0), HO - 1)) >> 3;
                const int y1 = (min(max(iy0 + 1, 0), HO - 1)) >> 3;
                const float w00 = (xv0 && yv0) ? (1.0f - wx_) * (1.0f - wy_) : 0.0f;
                const float w10 = (xv1 && yv0) ? wx_ * (1.0f - wy_) : 0.0f;
                const float w01 = (xv0 && yv1) ? (1.0f - wx_) * wy_ : 0.0f;
                const float w11 = (xv1 && yv1) ? wx_ * wy_ : 0.0f;
                v[k] = w00 * g[(y0 << 8) + x0]
                     + w10 * g[(y0 << 8) + x1]
                     + w01 * g[(y1 << 8) + x0]
                     + w11 * g[(y1 << 8) + x1];
            }
            ob[h] = make_float4(v[0], v[1], v[2], v[3]);
        }
    }
}
} // namespace

extern "C" void kernel_launch(void* const* d_in, const int* in_sizes, int n_in,
                              void* d_out, int out_size)
{
    const float* gt    = (const float*)d_in[0];
    const float* theta = (const float*)d_in[1];
    float* out = (float*)d_out;

    dim3 grid(WO / 128, HO / 16, NB);   // (16, 64, 8)
    stn_kernel<<<grid, 256>>>(gt, theta, out);
}

// round 17
// speedup vs baseline: 1.5068x; 1.5068x over previous
#include <cuda_runtime.h>
#include <cuda_bf16.h>

// STN_fixTheta: fused 8x nearest-upsample + dual bilinear grid_sample.
// gt: [8,1,128,256] f32, theta: [8,6] f32.
// out: box [8,1,1024,2048] f32 followed by boxy [8,1,1024,2048] f32.
//
// Thread tile = 2 rows x 8 px. One 3x3 gt texel window covers the whole tile
// in the common case (8x upsample => tiny texel footprint), amortizing 9 loads
// over 16 pixels. boxy computed + stored up front (branch-uniform memory ops —
// divergent-replicated LDG/STG multiplied L1 wavefronts in the R11 attempt).

namespace {
constexpr int NB  = 8;
constexpr int HIN = 128;
constexpr int WIN = 256;
constexpr int HO  = 1024;
constexpr int WO  = 2048;

// floor via 2^23 bias (no cvt-pipe ops)
__device__ __forceinline__ void ffloor(float x, float& f, int& i) {
    const float MAGIC = 12582912.0f;            // 1.5 * 2^23
    float tt = x + MAGIC;
    float r  = tt - MAGIC;
    int   ri = __float_as_int(tt) - 0x4B400000;
    if (r > x) { r -= 1.0f; ri -= 1; }
    f = r; i = ri;
}

__global__ __launch_bounds__(256, 6) void stn_kernel(
    const float* __restrict__ gt,
    const float* __restrict__ theta,
    float* __restrict__ out)
{
    const int tid  = threadIdx.x;
    const int w    = tid >> 5;
    const int lane = tid & 31;
    const int lx   = lane & 7;           // 8 lanes in x
    const int ly   = lane >> 3;          // 4 row-pairs in y
    const int wx   = w & 1;
    const int wy   = w >> 1;

    // block tile: 128 px wide x 32 rows; thread tile: 8 px x 2 rows
    const int xo0 = blockIdx.x * 128 + wx * 64 + lx * 8;
    const int yo0 = blockIdx.y * 32  + wy * 8  + ly * 2;
    const int b   = blockIdx.z;

    const float2 th01 = __ldg(reinterpret_cast<const float2*>(theta + b * 6 + 0));
    const float2 th23 = __ldg(reinterpret_cast<const float2*>(theta + b * 6 + 2));
    const float2 th45 = __ldg(reinterpret_cast<const float2*>(theta + b * 6 + 4));
    const float t0 = th01.x, t1 = th01.y, t2 = th23.x, t3 = th23.y;
    const float t4 = th45.x, t5 = th45.y;

    const float* __restrict__ g = gt + b * (HIN * WIN);
    const long long pix0 = ((long long)b * HO + yo0) * WO + xo0;

    float ysr[2];
    ysr[0] = (yo0 + 0.5f) * (2.0f / HO) - 1.0f;
    ysr[1] = (yo0 + 1.5f) * (2.0f / HO) - 1.0f;

    // ---------------- boxy: both rows, compute AND store immediately --------
    #pragma unroll
    for (int r = 0; r < 2; ++r) {
        const float gyy = fmaf(t4, ysr[r], t5);
        const float iyy = (fmaf(gyy, (float)HO, (float)HO) - 1.0f) * 0.5f;
        float iy0f; int iy0y;
        ffloor(iyy, iy0f, iy0y);
        const float wyy = iyy - iy0f;
        const bool ok0  = (unsigned)iy0y < (unsigned)HO;
        const bool ok1  = (unsigned)(iy0y + 1) < (unsigned)HO;
        float vy = 0.0f;
        if (ok0 | ok1) {
            const int   xc  = xo0 >> 3;
            const int   ry0 = (min(max(iy0y, 0), HO - 1)) >> 3;
            const int   ry1 = (min(max(iy0y + 1, 0), HO - 1)) >> 3;
            const float wA  = ok0 ? (1.0f - wyy) : 0.0f;
            const float wB  = ok1 ? wyy : 0.0f;
            vy = wA * g[ry0 * WIN + xc] + wB * g[ry1 * WIN + xc];
        }
        float4* oy = reinterpret_cast<float4*>(out + (long long)NB * HO * WO + pix0 + (long long)r * WO);
        const float4 vy4 = make_float4(vy, vy, vy, vy);
        oy[0] = vy4;
        oy[1] = vy4;
    }

    // ---------------- box: per-row bases (full formula, exact) --------------
    const float xs0 = (xo0 + 0.5f) * (2.0f / WO) - 1.0f;
    float ixbr[2], iybr[2];
    #pragma unroll
    for (int r = 0; r < 2; ++r) {
        const float gx0 = fmaf(t0, xs0, fmaf(t1, ysr[r], t2));
        const float gy0 = fmaf(t3, xs0, fmaf(t4, ysr[r], t5));
        ixbr[r] = (fmaf(gx0, (float)WO, (float)WO) - 1.0f) * 0.5f;
        iybr[r] = (fmaf(gy0, (float)HO, (float)HO) - 1.0f) * 0.5f;
    }
    const float sx = t0;           // d ix / d xo
    const float sy = t3 * 0.5f;    // d iy / d xo

    // combined bbox over both rows
    const float dx7 = 7.0f * sx, dy7 = 7.0f * sy;
    const float ixm0 = fminf(ixbr[0], ixbr[0] + dx7), ixM0 = fmaxf(ixbr[0], ixbr[0] + dx7);
    const float ixm1 = fminf(ixbr[1], ixbr[1] + dx7), ixM1 = fmaxf(ixbr[1], ixbr[1] + dx7);
    const float iym0 = fminf(iybr[0], iybr[0] + dy7), iyM0 = fmaxf(iybr[0], iybr[0] + dy7);
    const float iym1 = fminf(iybr[1], iybr[1] + dy7), iyM1 = fmaxf(iybr[1], iybr[1] + dy7);
    const float ixmin = fminf(ixm0, ixm1), ixmax = fmaxf(ixM0, ixM1);
    const float iymin = fminf(iym0, iym1), iymax = fmaxf(iyM0, iyM1);

    const bool interior = (ixmin >= 0.0f) && (ixmax < (float)(WO - 1)) &&
                          (iymin >= 0.0f) && (iymax < (float)(HO - 1));

    if (ixmax < -1.0f || ixmin >= (float)WO || iymax < -1.0f || iymin >= (float)HO) {
        const float4 z = make_float4(0.0f, 0.0f, 0.0f, 0.0f);
        #pragma unroll
        for (int r = 0; r < 2; ++r) {
            float4* ob = reinterpret_cast<float4*>(out + pix0 + (long long)r * WO);
            ob[0] = z;
            ob[1] = z;
        }
        return;
    }

    if (interior) {
        const int xlo = ((int)ixmin) >> 3;
        const int xhi = (((int)ixmax) + 1) >> 3;
        const int ylo = ((int)iymin) >> 3;
        const int yhi = (((int)iymax) + 1) >> 3;

        if ((xhi - xlo) <= 2 && (yhi - ylo) <= 2) {
            // -------- register 3x3 fast path shared by both rows --------
            const int x1i = min(xlo + 1, WIN - 1);
            const int x2i = min(xlo + 2, WIN - 1);
            const int y1i = min(ylo + 1, HIN - 1);
            const int y2i = min(ylo + 2, HIN - 1);
            const float* r0p = g + ylo * WIN;
            const float* r1p = g + y1i * WIN;
            const float* r2p = g + y2i * WIN;
            const float a00 = r0p[xlo], a01 = r0p[x1i], a02 = r0p[x2i];
            const float a10 = r1p[xlo], a11 = r1p[x1i], a12 = r1p[x2i];
            const float a20 = r2p[xlo], a21 = r2p[x1i], a22 = r2p[x2i];
            const float d00 = a01 - a00, d01 = a02 - a01;
            const float d10 = a11 - a10, d11 = a12 - a11;
            const float d20 = a21 - a20, d21 = a22 - a21;
            const float cx1 = (float)(8 * xlo + 7), cx2 = cx1 + 8.0f;
            const float cy1 = (float)(8 * ylo + 7), cy2 = cy1 + 8.0f;
            #pragma unroll
            for (int r = 0; r < 2; ++r) {
                float4* ob = reinterpret_cast<float4*>(out + pix0 + (long long)r * WO);
                #pragma unroll
                for (int h = 0; h < 2; ++h) {
                    float v[4];
                    #pragma unroll
                    for (int k = 0; k < 4; ++k) {
                        const int   j   = h * 4 + k;
                        const float ix  = fmaf((float)j, sx, ixbr[r]);
                        const float iy  = fmaf((float)j, sy, iybr[r]);
                        const float Wx1 = __saturatef(ix - cx1);
                        const float Wx2 = __saturatef(ix - cx2);
                        const float Wy1 = __saturatef(iy - cy1);
                        const float Wy2 = __saturatef(iy - cy2);
                        const float u0 = fmaf(Wx2, d01, fmaf(Wx1, d00, a00));
                        const float u1 = fmaf(Wx2, d11, fmaf(Wx1, d10, a10));
                        const float u2 = fmaf(Wx2, d21, fmaf(Wx1, d20, a20));
                        const float vv = fmaf(Wy1, u1 - u0, u0);
                        v[k] = fmaf(Wy2, u2 - u1, vv);
                    }
                    ob[h] = make_float4(v[0], v[1], v[2], v[3]);
                }
            }
        } else {
            // -------- generic interior (batched global loads), per row ------
            #pragma unroll
            for (int r = 0; r < 2; ++r) {
                float4* ob = reinterpret_cast<float4*>(out + pix0 + (long long)r * WO);
                #pragma unroll
                for (int h = 0; h < 2; ++h) {
                    int   o00[4], o10[4], o01[4], o11[4];
                    float fwx[4], fwy[4];
                    #pragma unroll
                    for (int k = 0; k < 4; ++k) {
                        const int   j  = h * 4 + k;
                        const float ix = fmaf((float)j, sx, ixbr[r]);
                        const float iy = fmaf((float)j, sy, iybr[r]);
                        float fx, fy; int ix0, iy0;
                        ffloor(ix, fx, ix0);
                        ffloor(iy, fy, iy0);
                        fwx[k] = ix - fx;
                        fwy[k] = iy - fy;
                        const int x0 = ix0 >> 3;
                        const int x1 = (ix0 + 1) >> 3;
                        const int y0 = iy0 >> 3;
                        const int y1 = (iy0 + 1) >> 3;
                        o00[k] = (y0 << 8) + x0;
                        o10[k] = (y0 << 8) + x1;
                        o01[k] = (y1 << 8) + x0;
                        o11[k] = (y1 << 8) + x1;
                    }
                    float l00[4], l10[4], l01[4], l11[4];
                    #pragma unroll
                    for (int k = 0; k < 4; ++k) {
                        l00[k] = g[o00[k]];
                        l10[k] = g[o10[k]];
                        l01[k] = g[o01[k]];
                        l11[k] = g[o11[k]];
                    }
                    float v[4];
                    #pragma unroll
                    for (int k = 0; k < 4; ++k) {
                        const float a  = fmaf(fwx[k], l10[k] - l00[k], l00[k]);
                        const float cc = fmaf(fwx[k], l11[k] - l01[k], l01[k]);
                        v[k] = fmaf(fwy[k], cc - a, a);
                    }
                    ob[h] = make_float4(v[0], v[1], v[2], v[3]);
                }
            }
        }
    } else {
        // -------- edge/mixed: general predicated path (rare), per row -------
        #pragma unroll
        for (int r = 0; r < 2; ++r) {
            float4* ob = reinterpret_cast<float4*>(out + pix0 + (long long)r * WO);
            #pragma unroll
            for (int h = 0; h < 2; ++h) {
                float v[4];
                #pragma unroll
                for (int k = 0; k < 4; ++k) {
                    const int   j  = h * 4 + k;
                    const float ix = fmaf((float)j, sx, ixbr[r]);
                    const float iy = fmaf((float)j, sy, iybr[r]);
                    float fx, fy; int ix0, iy0;
                    ffloor(ix, fx, ix0);
                    ffloor(iy, fy, iy0);
                    const float wx_ = ix - fx;
                    const float wy_ = iy - fy;
                    const bool xv0 = (unsigned)ix0       < (unsigned)WO;
                    const bool xv1 = (unsigned)(ix0 + 1) < (unsigned)WO;
                    const bool yv0 = (unsigned)iy0       < (unsigned)HO;
                    const bool yv1 = (unsigned)(iy0 + 1) < (unsigned)HO;
                    const int x0 = (min(max(ix0, 0), WO - 1)) >> 3;
                    const int x1 = (min(max(ix0 + 1, 0), WO - 1)) >> 3;
                    const int y0 = (min(max(iy0, 0), HO - 1)) >> 3;
                    const int y1 = (min(max(iy0 + 1, 0), HO - 1)) >> 3;
                    const float w00 = (xv0 && yv0) ? (1.0f - wx_) * (1.0f - wy_) : 0.0f;
                    const float w10 = (xv1 && yv0) ? wx_ * (1.0f - wy_) : 0.0f;
                    const float w01 = (xv0 && yv1) ? (1.0f - wx_) * wy_ : 0.0f;
                    const float w11 = (xv1 && yv1) ? wx_ * wy_ : 0.0f;
                    v[k] = w00 * g[(y0 << 8) + x0]
                         + w10 * g[(y0 << 8) + x1]
                         + w01 * g[(y1 << 8) + x0]
                         + w11 * g[(y1 << 8) + x1];
                }
                ob[h] = make_float4(v[0], v[1], v[2], v[3]);
            }
        }
    }
}
} // namespace

extern "C" void kernel_launch(void* const* d_in, const int* in_sizes, int n_in,
                              void* d_out, int out_size)
{
    const float* gt    = (const float*)d_in[0];
    const float* theta = (const float*)d_in[1];
    float* out = (float*)d_out;

    dim3 grid(WO / 128, HO / 32, NB);   // (16, 32, 8)
    stn_kernel<<<grid, 256>>>(gt, theta, out);
}